// round 5
// baseline (speedup 1.0000x reference)
#include <cuda_runtime.h>
#include <math.h>
#include <stdint.h>

#define Bz     4
#define Tt     2048
#define Dm     1024
#define Hh     16
#define Dh     64
#define Mrows  (Bz * Tt)     // 8192

__device__ float g_Q[Mrows * Dm];
__device__ float g_K[Mrows * Dm];
__device__ float g_V[Mrows * Dm];
__device__ float g_ctx[Mrows * Dm];

__device__ __forceinline__ uint32_t f2tf32(float x) {
    uint32_t r;
    asm("cvt.rna.tf32.f32 %0, %1;" : "=r"(r) : "f"(x));
    return r;
}

__device__ __forceinline__ void cp16(void* dst_smem, const void* src) {
    uint32_t d = (uint32_t)__cvta_generic_to_shared(dst_smem);
    asm volatile("cp.async.cg.shared.global [%0], [%1], 16;\n" :: "r"(d), "l"(src));
}
#define CP_COMMIT() asm volatile("cp.async.commit_group;\n" ::: "memory")
#define CP_WAIT1()  asm volatile("cp.async.wait_group 1;\n" ::: "memory")

// ================== tf32 tensor-core GEMM, 2-stage cp.async pipeline ==================
// C[M,N] = A[M,K]*B[K,N]; block 128x128, BK=32, 8 warps (4x2), warp tile 32x64.
#define BM 128
#define BN 128
#define BK 32
#define AS_STRIDE 36
#define BS_STRIDE 136
#define ASTGW (BM * AS_STRIDE)     // words per A stage
#define BSTGW (BK * BS_STRIDE)     // words per B stage
#define GEMM_SMEM_BYTES ((2 * (ASTGW + BSTGW)) * 4)
#define KITERS (Dm / BK)           // 32

__device__ __forceinline__ void gemm_tf32_body(const float* __restrict__ A,
                                               const float* __restrict__ B,
                                               float* __restrict__ C)
{
    extern __shared__ float gsm[];
    float* As = gsm;                // [2][ASTGW] raw fp32
    float* Bs = gsm + 2 * ASTGW;    // [2][BSTGW] raw fp32

    const int tid  = threadIdx.x;
    const int lane = tid & 31;
    const int warp = tid >> 5;
    const int wm   = warp >> 1;
    const int wn   = warp & 1;
    const int bM = blockIdx.y * BM;
    const int bN = blockIdx.x * BN;
    const int ar = lane >> 2;
    const int ac = lane & 3;

    const float* Ablk = A + (size_t)bM * Dm;
    const float* Bblk = B + bN;

    // staging indices (per thread: 4 float4 for A, 4 for B)
    const int aRow = tid >> 1;            // wrong granularity for 1024 f4 — recompute below per i

    float acc[2][8][4];
    #pragma unroll
    for (int mt = 0; mt < 2; mt++)
        #pragma unroll
        for (int nt = 0; nt < 8; nt++)
            #pragma unroll
            for (int i = 0; i < 4; i++) acc[mt][nt][i] = 0.f;
    (void)aRow;

    auto stage = [&](int k0, int buf) {
        float* Ad = As + buf * ASTGW;
        float* Bd = Bs + buf * BSTGW;
        #pragma unroll
        for (int i = 0; i < 4; i++) {
            int f   = tid + i * 256;
            int row = f >> 3;             // 8 float4 per A row
            int c4  = (f & 7) * 4;
            cp16(Ad + row * AS_STRIDE + c4, Ablk + (size_t)row * Dm + k0 + c4);
        }
        #pragma unroll
        for (int i = 0; i < 4; i++) {
            int f   = tid + i * 256;
            int row = f >> 5;             // 32 float4 per B row
            int c4  = (f & 31) * 4;
            cp16(Bd + row * BS_STRIDE + c4, Bblk + (size_t)(k0 + row) * Dm + c4);
        }
    };

    stage(0, 0);
    CP_COMMIT();

    for (int it = 0; it < KITERS; it++) {
        const int buf = it & 1;
        if (it + 1 < KITERS) stage((it + 1) * BK, buf ^ 1);
        CP_COMMIT();
        CP_WAIT1();
        __syncthreads();

        const float* Ab = As + buf * ASTGW;
        const float* Bb = Bs + buf * BSTGW;
        #pragma unroll
        for (int k8 = 0; k8 < BK / 8; k8++) {
            const int k = k8 * 8;
            uint32_t afrag[2][4];
            #pragma unroll
            for (int mt = 0; mt < 2; mt++) {
                const int mo = wm * 32 + mt * 16;
                afrag[mt][0] = f2tf32(Ab[(mo + ar    ) * AS_STRIDE + k + ac]);
                afrag[mt][1] = f2tf32(Ab[(mo + ar + 8) * AS_STRIDE + k + ac]);
                afrag[mt][2] = f2tf32(Ab[(mo + ar    ) * AS_STRIDE + k + ac + 4]);
                afrag[mt][3] = f2tf32(Ab[(mo + ar + 8) * AS_STRIDE + k + ac + 4]);
            }
            #pragma unroll
            for (int nt = 0; nt < 8; nt++) {
                const int no = wn * 64 + nt * 8;
                uint32_t b0 = f2tf32(Bb[(k + ac    ) * BS_STRIDE + no + ar]);
                uint32_t b1 = f2tf32(Bb[(k + ac + 4) * BS_STRIDE + no + ar]);
                #pragma unroll
                for (int mt = 0; mt < 2; mt++) {
                    asm volatile(
                        "mma.sync.aligned.m16n8k8.row.col.f32.tf32.tf32.f32 "
                        "{%0,%1,%2,%3}, {%4,%5,%6,%7}, {%8,%9}, {%0,%1,%2,%3};\n"
                        : "+f"(acc[mt][nt][0]), "+f"(acc[mt][nt][1]),
                          "+f"(acc[mt][nt][2]), "+f"(acc[mt][nt][3])
                        : "r"(afrag[mt][0]), "r"(afrag[mt][1]),
                          "r"(afrag[mt][2]), "r"(afrag[mt][3]),
                          "r"(b0), "r"(b1));
                }
            }
        }
        __syncthreads();
    }

    #pragma unroll
    for (int mt = 0; mt < 2; mt++) {
        const int row0 = bM + wm * 32 + mt * 16 + ar;
        #pragma unroll
        for (int nt = 0; nt < 8; nt++) {
            const int col = bN + wn * 64 + nt * 8 + ac * 2;
            *(float2*)(C + (size_t)row0 * Dm + col)       = make_float2(acc[mt][nt][0], acc[mt][nt][1]);
            *(float2*)(C + (size_t)(row0 + 8) * Dm + col) = make_float2(acc[mt][nt][2], acc[mt][nt][3]);
        }
    }
}

__global__ __launch_bounds__(256, 2) void gemm_qkv(const float* __restrict__ x,
                                                   const float* __restrict__ Wq,
                                                   const float* __restrict__ Wk,
                                                   const float* __restrict__ Wv)
{
    const float* W = (blockIdx.z == 0) ? Wq : (blockIdx.z == 1) ? Wk : Wv;
    float*       C = (blockIdx.z == 0) ? g_Q : (blockIdx.z == 1) ? g_K : g_V;
    gemm_tf32_body(x, W, C);
}

__global__ __launch_bounds__(256, 2) void gemm_out(const float* __restrict__ Wo,
                                                   float* __restrict__ out)
{
    gemm_tf32_body(g_ctx, Wo, out);
}

// ======================= tensor-core causal flash attention =======================
// 256 threads (8 warps); warp w owns 16 query rows (1 m16 tile). 128 q rows/CTA.
#define QS 68
#define KS 68
#define VS 72
#define PS 68
#define ATTN_SMEM_WORDS (128*QS + 64*KS + 64*VS + 128*PS)
#define ATTN_SMEM_BYTES (ATTN_SMEM_WORDS * 4)

__global__ __launch_bounds__(256, 2) void attn_mma()
{
    extern __shared__ uint32_t smw[];
    uint32_t* Qs  = smw;                 // 128 x QS (tf32)
    uint32_t* Ksm = Qs  + 128 * QS;      // 64 x KS
    uint32_t* Vsm = Ksm + 64 * KS;       // 64 x VS
    uint32_t* Psm = Vsm + 64 * VS;       // 8 warps x 16 x PS

    const int tid  = threadIdx.x;
    const int lane = tid & 31;
    const int warp = tid >> 5;           // 0..7
    const int ar   = lane >> 2;
    const int ac   = lane & 3;

    const int qt = blockIdx.x, h = blockIdx.y, b = blockIdx.z;
    const int q0 = qt * 128;

    // ---- stage Q tile (scale folded), 128x64 = 2048 float4 / 256 thr ----
    const float* Qg = g_Q + ((size_t)(b * Tt + q0)) * Dm + h * Dh;
    #pragma unroll
    for (int i = 0; i < 8; i++) {
        int f = tid + i * 256;
        int row = f >> 4;
        int c4  = (f & 15) * 4;
        float4 v = *(const float4*)(Qg + (size_t)row * Dm + c4);
        uint32_t* d = &Qs[row * QS + c4];
        d[0] = f2tf32(v.x * 0.125f); d[1] = f2tf32(v.y * 0.125f);
        d[2] = f2tf32(v.z * 0.125f); d[3] = f2tf32(v.w * 0.125f);
    }

    float accO[8][4];
    #pragma unroll
    for (int nt = 0; nt < 8; nt++)
        #pragma unroll
        for (int i = 0; i < 4; i++) accO[nt][i] = 0.f;

    float mrow0 = -1e30f, mrow1 = -1e30f, lrow0 = 0.f, lrow1 = 0.f;

    uint32_t* Pw = Psm + warp * 16 * PS;
    const int ntiles = 2 * qt + 2;

    for (int kt = 0; kt < ntiles; kt++) {
        const size_t kvbase = ((size_t)(b * Tt + kt * 64)) * Dm + h * Dh;
        __syncthreads();
        #pragma unroll
        for (int i = 0; i < 4; i++) {
            int f = tid + i * 256;
            int row = f >> 4;
            int c4  = (f & 15) * 4;
            float4 kv = *(const float4*)(g_K + kvbase + (size_t)row * Dm + c4);
            uint32_t* dk = &Ksm[row * KS + c4];
            dk[0] = f2tf32(kv.x); dk[1] = f2tf32(kv.y);
            dk[2] = f2tf32(kv.z); dk[3] = f2tf32(kv.w);
            float4 vv = *(const float4*)(g_V + kvbase + (size_t)row * Dm + c4);
            uint32_t* dv = &Vsm[row * VS + c4];
            dv[0] = f2tf32(vv.x); dv[1] = f2tf32(vv.y);
            dv[2] = f2tf32(vv.z); dv[3] = f2tf32(vv.w);
        }
        __syncthreads();

        // ---- S = Q K^T (warp: 16 x 64) ----
        float s[8][4];
        #pragma unroll
        for (int nt = 0; nt < 8; nt++)
            #pragma unroll
            for (int i = 0; i < 4; i++) s[nt][i] = 0.f;

        #pragma unroll
        for (int k8 = 0; k8 < 8; k8++) {
            const int k = k8 * 8;
            const int mo = warp * 16;
            uint32_t a0 = Qs[(mo + ar    ) * QS + k + ac];
            uint32_t a1 = Qs[(mo + ar + 8) * QS + k + ac];
            uint32_t a2 = Qs[(mo + ar    ) * QS + k + ac + 4];
            uint32_t a3 = Qs[(mo + ar + 8) * QS + k + ac + 4];
            #pragma unroll
            for (int nt = 0; nt < 8; nt++) {
                const int n = nt * 8;
                uint32_t b0 = Ksm[(n + ar) * KS + k + ac];
                uint32_t b1 = Ksm[(n + ar) * KS + k + ac + 4];
                asm volatile(
                    "mma.sync.aligned.m16n8k8.row.col.f32.tf32.tf32.f32 "
                    "{%0,%1,%2,%3}, {%4,%5,%6,%7}, {%8,%9}, {%0,%1,%2,%3};\n"
                    : "+f"(s[nt][0]), "+f"(s[nt][1]), "+f"(s[nt][2]), "+f"(s[nt][3])
                    : "r"(a0), "r"(a1), "r"(a2), "r"(a3), "r"(b0), "r"(b1));
            }
        }

        // ---- mask (edge tiles) + online softmax ----
        const int r0 = q0 + warp * 16 + ar;
        if (kt >= 2 * qt) {
            #pragma unroll
            for (int nt = 0; nt < 8; nt++) {
                const int c0 = kt * 64 + nt * 8 + 2 * ac;
                if (c0     > r0    ) s[nt][0] = -1e30f;
                if (c0 + 1 > r0    ) s[nt][1] = -1e30f;
                if (c0     > r0 + 8) s[nt][2] = -1e30f;
                if (c0 + 1 > r0 + 8) s[nt][3] = -1e30f;
            }
        }
        float mx0 = -1e30f, mx1 = -1e30f;
        #pragma unroll
        for (int nt = 0; nt < 8; nt++) {
            mx0 = fmaxf(mx0, fmaxf(s[nt][0], s[nt][1]));
            mx1 = fmaxf(mx1, fmaxf(s[nt][2], s[nt][3]));
        }
        mx0 = fmaxf(mx0, __shfl_xor_sync(0xffffffff, mx0, 1));
        mx0 = fmaxf(mx0, __shfl_xor_sync(0xffffffff, mx0, 2));
        mx1 = fmaxf(mx1, __shfl_xor_sync(0xffffffff, mx1, 1));
        mx1 = fmaxf(mx1, __shfl_xor_sync(0xffffffff, mx1, 2));

        const float mn0 = fmaxf(mrow0, mx0);
        const float mn1 = fmaxf(mrow1, mx1);
        const float corr0 = __expf(mrow0 - mn0);
        const float corr1 = __expf(mrow1 - mn1);
        mrow0 = mn0; mrow1 = mn1;

        float ls0 = 0.f, ls1 = 0.f;
        #pragma unroll
        for (int nt = 0; nt < 8; nt++) {
            float p00 = __expf(s[nt][0] - mn0);
            float p01 = __expf(s[nt][1] - mn0);
            float p10 = __expf(s[nt][2] - mn1);
            float p11 = __expf(s[nt][3] - mn1);
            ls0 += p00 + p01;
            ls1 += p10 + p11;
            uint32_t* pw = Pw + ar * PS + nt * 8 + 2 * ac;
            pw[0]          = f2tf32(p00);
            pw[1]          = f2tf32(p01);
            pw[8 * PS]     = f2tf32(p10);
            pw[8 * PS + 1] = f2tf32(p11);
        }
        ls0 += __shfl_xor_sync(0xffffffff, ls0, 1);
        ls0 += __shfl_xor_sync(0xffffffff, ls0, 2);
        ls1 += __shfl_xor_sync(0xffffffff, ls1, 1);
        ls1 += __shfl_xor_sync(0xffffffff, ls1, 2);
        lrow0 = lrow0 * corr0 + ls0;
        lrow1 = lrow1 * corr1 + ls1;

        #pragma unroll
        for (int nt = 0; nt < 8; nt++) {
            accO[nt][0] *= corr0; accO[nt][1] *= corr0;
            accO[nt][2] *= corr1; accO[nt][3] *= corr1;
        }
        __syncwarp();

        // ---- O += P V (warp: 16 x 64, K=64) ----
        #pragma unroll
        for (int k8 = 0; k8 < 8; k8++) {
            const int k = k8 * 8;
            uint32_t a0 = Pw[(ar    ) * PS + k + ac];
            uint32_t a1 = Pw[(ar + 8) * PS + k + ac];
            uint32_t a2 = Pw[(ar    ) * PS + k + ac + 4];
            uint32_t a3 = Pw[(ar + 8) * PS + k + ac + 4];
            #pragma unroll
            for (int nt = 0; nt < 8; nt++) {
                const int n = nt * 8;
                uint32_t b0 = Vsm[(k + ac    ) * VS + n + ar];
                uint32_t b1 = Vsm[(k + ac + 4) * VS + n + ar];
                asm volatile(
                    "mma.sync.aligned.m16n8k8.row.col.f32.tf32.tf32.f32 "
                    "{%0,%1,%2,%3}, {%4,%5,%6,%7}, {%8,%9}, {%0,%1,%2,%3};\n"
                    : "+f"(accO[nt][0]), "+f"(accO[nt][1]),
                      "+f"(accO[nt][2]), "+f"(accO[nt][3])
                    : "r"(a0), "r"(a1), "r"(a2), "r"(a3), "r"(b0), "r"(b1));
            }
        }
    }

    // ---- normalize + store ----
    const float inv0 = 1.f / lrow0;
    const float inv1 = 1.f / lrow1;
    const int r0 = q0 + warp * 16 + ar;
    float* og = g_ctx + ((size_t)(b * Tt)) * Dm + h * Dh;
    #pragma unroll
    for (int nt = 0; nt < 8; nt++) {
        const int col = nt * 8 + 2 * ac;
        *(float2*)(og + (size_t)r0 * Dm + col) =
            make_float2(accO[nt][0] * inv0, accO[nt][1] * inv0);
        *(float2*)(og + (size_t)(r0 + 8) * Dm + col) =
            make_float2(accO[nt][2] * inv1, accO[nt][3] * inv1);
    }
}

// ======================= launch =======================
extern "C" void kernel_launch(void* const* d_in, const int* in_sizes, int n_in,
                              void* d_out, int out_size)
{
    const float* x  = (const float*)d_in[0];
    const float* Wq = (const float*)d_in[1];
    const float* Wk = (const float*)d_in[2];
    const float* Wv = (const float*)d_in[3];
    const float* Wo = (const float*)d_in[4];
    float* out = (float*)d_out;

    static int attr_done = 0;
    if (!attr_done) {
        cudaFuncSetAttribute(gemm_qkv, cudaFuncAttributeMaxDynamicSharedMemorySize, GEMM_SMEM_BYTES);
        cudaFuncSetAttribute(gemm_out, cudaFuncAttributeMaxDynamicSharedMemorySize, GEMM_SMEM_BYTES);
        cudaFuncSetAttribute(attn_mma, cudaFuncAttributeMaxDynamicSharedMemorySize, ATTN_SMEM_BYTES);
        attr_done = 1;
    }

    dim3 gQKV(Dm / BN, Mrows / BM, 3);
    gemm_qkv<<<gQKV, 256, GEMM_SMEM_BYTES>>>(x, Wq, Wk, Wv);

    dim3 gA(Tt / 128, Hh, Bz);
    attn_mma<<<gA, 256, ATTN_SMEM_BYTES>>>();

    dim3 gO(Dm / BN, Mrows / BM, 1);
    gemm_out<<<gO, 256, GEMM_SMEM_BYTES>>>(Wo, out);
}